// round 10
// baseline (speedup 1.0000x reference)
#include <cuda_runtime.h>
#include <cuda_bf16.h>
#include <math.h>

#define HID 512
#define SEQ 784
#define BATCH 1024
#define OUT 10
#define BT 8          // batch rows per CTA
#define NCTA (BATCH/BT)
#define JC 90         // At rows cached in SMEM

// ---------------- device-global scratch (static: allocation-free) ----------
__device__ double g_BL[HID * HID];      // (I - s/2 A)^-1, fp64
__device__ float  g_At[HID * HID];      // Ad transposed: At[j][i] = Ad[i][j]
__device__ float  g_Bd[HID];
__device__ float  g_M2[HID * OUT];      // C1^T @ W

// ---------------- f32x2 helpers (packed double-rate fp32) ------------------
__device__ __forceinline__ unsigned long long pk2(float a) {
    unsigned long long r;
    asm("mov.b64 %0,{%1,%1};" : "=l"(r) : "f"(a));
    return r;
}
__device__ __forceinline__ unsigned long long mul2(unsigned long long a, unsigned long long b) {
    unsigned long long r;
    asm("mul.rn.f32x2 %0,%1,%2;" : "=l"(r) : "l"(a), "l"(b));
    return r;
}
__device__ __forceinline__ void fma2(unsigned long long& d, unsigned long long a, unsigned long long b) {
    asm("fma.rn.f32x2 %0,%1,%2,%0;" : "+l"(d) : "l"(a), "l"(b));
}
__device__ __forceinline__ float2 up2(unsigned long long v) {
    float2 f;
    asm("mov.b64 {%0,%1},%2;" : "=f"(f.x), "=f"(f.y) : "l"(v));
    return f;
}

// ---------------- prep 1: BL = (I - s/2 A)^-1 via O(N) column recurrence ---
// A is lower-triangular: A[i][j] = -P_i P_j (i>j), A[i][i] = -(i+1), P_i = sqrt(1+2i).
// M[i][j] = (s/2) P_i P_j (i>j), diag d_i = 1 + (s/2)(i+1).
// Column c: x_c = 1/d_c; S = P_c x_c; for i>c: x_i = -(s/2) P_i S / d_i; S += P_i x_i.
__global__ void prep_BL() {
    __shared__ double P[HID], dinv[HID];
    const int t = threadIdx.x;
    const double s2 = 0.5 / (double)SEQ;
    P[t]    = sqrt(1.0 + 2.0 * (double)t);
    dinv[t] = 1.0 / (1.0 + s2 * (double)(t + 1));
    __syncthreads();
    const int c = t;
    double xv = dinv[c];
    g_BL[c * HID + c] = xv;
    double S = P[c] * xv;
    for (int i = c + 1; i < HID; i++) {
        double xi = -(s2 * P[i] * S) * dinv[i];
        g_BL[i * HID + c] = xi;
        S += P[i] * xi;
    }
}

// ---------------- prep 2: Ad = BL @ (I + s/2 A) via per-row prefix scan ----
// Ad[i][j] = BL[i][j]*(1 - s2*(j+1)) - s2*P_j * (pre[i] - pre[j]),
// pre[j] = sum_{k<=j} BL[i][k] P_k;  Bd[i] = (1/SEQ) * pre[i].
__global__ void prep_Ad() {
    const int i = blockIdx.x;
    const int t = threadIdx.x;
    __shared__ double pre[HID];
    const double s2 = 0.5 / (double)SEQ;
    const double Pt = sqrt(1.0 + 2.0 * (double)t);
    const double bl = (t <= i) ? g_BL[i * HID + t] : 0.0;
    pre[t] = bl * Pt;
    __syncthreads();
    for (int off = 1; off < HID; off <<= 1) {
        double add = (t >= off) ? pre[t - off] : 0.0;
        __syncthreads();
        pre[t] += add;
        __syncthreads();
    }
    const double prei = pre[i];
    float at;
    if (t <= i) {
        double dplus = 1.0 - s2 * (double)(t + 1);
        at = (float)(bl * dplus - s2 * Pt * (prei - pre[t]));
    } else {
        at = 0.0f;
    }
    g_At[t * HID + i] = at;   // transposed store
    if (t == i) g_Bd[i] = (float)(prei / (double)SEQ);
}

// ---------------- prep 3: M2 = C1^T @ W  (512 x 10) ------------------------
__global__ void prep_M2(const float* __restrict__ C1, const float* __restrict__ W) {
    const int i = blockIdx.x;      // hidden index
    const int t = threadIdx.x;     // 256 threads
    float acc[OUT];
#pragma unroll
    for (int o = 0; o < OUT; o++) acc[o] = 0.0f;
    for (int k = t; k < HID; k += 256) {
        float c = C1[k * HID + i];
#pragma unroll
        for (int o = 0; o < OUT; o++) acc[o] += c * W[k * OUT + o];
    }
    __shared__ float red[8][OUT];
    const int w = t >> 5, l = t & 31;
#pragma unroll
    for (int o = 0; o < OUT; o++) {
        float v = acc[o];
        for (int s = 16; s; s >>= 1) v += __shfl_xor_sync(0xffffffffu, v, s);
        if (l == 0) red[w][o] = v;
    }
    __syncthreads();
    if (t < OUT) {
        float s = 0.0f;
        for (int w2 = 0; w2 < 8; w2++) s += red[w2][t];
        g_M2[i * OUT + t] = s;
    }
}

// ---------------- main persistent kernel: both SSM layers per batch tile ---
// smem: h[512][8] | y0[784][8] | u[8] | wred[16*8] | AtC[JC][512]
#define SMEM_FLOATS (HID*BT + SEQ*BT + 8 + 128 + JC*HID)
#define SMEM_BYTES (SMEM_FLOATS * 4)

__device__ __forceinline__ void step_compute(
    const float* usrc, const float* AtC, const float* h_sm,
    const float* __restrict__ Atg, int i, unsigned long long Bv2, float hr[BT])
{
    ulonglong2 uA = *reinterpret_cast<const ulonglong2*>(usrc);
    ulonglong2 uB = *reinterpret_cast<const ulonglong2*>(usrc + 4);
    unsigned long long a0 = mul2(Bv2, uA.x);
    unsigned long long a1 = mul2(Bv2, uA.y);
    unsigned long long a2 = mul2(Bv2, uB.x);
    unsigned long long a3 = mul2(Bv2, uB.y);
#pragma unroll 5
    for (int j = 0; j < JC; j++) {
        float a = AtC[j * HID + i];
        unsigned long long ad = pk2(a);
        ulonglong2 hA = *reinterpret_cast<const ulonglong2*>(h_sm + j * BT);
        ulonglong2 hB = *reinterpret_cast<const ulonglong2*>(h_sm + j * BT + 4);
        fma2(a0, ad, hA.x); fma2(a1, ad, hA.y);
        fma2(a2, ad, hB.x); fma2(a3, ad, hB.y);
    }
    const float* ag = Atg;   // = g_At + JC*HID + i
#pragma unroll 4
    for (int j = JC; j < HID; j++) {
        float a = __ldg(ag); ag += HID;
        unsigned long long ad = pk2(a);
        ulonglong2 hA = *reinterpret_cast<const ulonglong2*>(h_sm + j * BT);
        ulonglong2 hB = *reinterpret_cast<const ulonglong2*>(h_sm + j * BT + 4);
        fma2(a0, ad, hA.x); fma2(a1, ad, hA.y);
        fma2(a2, ad, hB.x); fma2(a3, ad, hB.y);
    }
    float2 f;
    f = up2(a0); hr[0] = tanhf(f.x); hr[1] = tanhf(f.y);
    f = up2(a1); hr[2] = tanhf(f.x); hr[3] = tanhf(f.y);
    f = up2(a2); hr[4] = tanhf(f.x); hr[5] = tanhf(f.y);
    f = up2(a3); hr[6] = tanhf(f.x); hr[7] = tanhf(f.y);
}

__global__ void __launch_bounds__(512, 1) ssm_main(
    const float* __restrict__ x, const float* __restrict__ C0,
    const float* __restrict__ bias, float* __restrict__ out)
{
    extern __shared__ float sm[];
    float* h_sm  = sm;                       // HID*BT
    float* y0_sm = sm + HID * BT;            // SEQ*BT
    float* u_sm  = y0_sm + SEQ * BT;         // 8
    float* wred  = u_sm + 8;                 // 16*8
    float* AtC   = wred + 128;               // JC*HID

    const int i  = threadIdx.x;
    const int b0 = blockIdx.x * BT;
    const int warp = i >> 5, lane = i & 31;

    for (int idx = i; idx < JC * HID; idx += 512) AtC[idx] = g_At[idx];
    for (int idx = i; idx < HID * BT; idx += 512) h_sm[idx] = 0.0f;

    const float Bv = g_Bd[i];
    const float c0 = C0[i];
    const unsigned long long Bv2 = pk2(Bv);
    const float* Atg = g_At + (size_t)JC * HID + i;

    if (i < BT) u_sm[i] = x[(b0 + i) * SEQ + 0];
    __syncthreads();

    // ---------------- LAYER 1 ----------------
    for (int t = 0; t < SEQ; t++) {
        float hr[BT];
        step_compute(u_sm, AtC, h_sm, Atg, i, Bv2, hr);

        // y0 partials: y0[b] = sum_i C0[i]*h[b][i]
        float p[BT];
#pragma unroll
        for (int b = 0; b < BT; b++) {
            float v = c0 * hr[b];
            for (int s = 16; s; s >>= 1) v += __shfl_xor_sync(0xffffffffu, v, s);
            p[b] = v;
        }
        if (lane == 0) {
#pragma unroll
            for (int b = 0; b < BT; b++) wred[warp * BT + b] = p[b];
        }
        __syncthreads();   // sync1: all reads of old h/u done; wred written

        *reinterpret_cast<float4*>(h_sm + i * BT)     = make_float4(hr[0], hr[1], hr[2], hr[3]);
        *reinterpret_cast<float4*>(h_sm + i * BT + 4) = make_float4(hr[4], hr[5], hr[6], hr[7]);

        if (i < BT) {
            float s = 0.0f;
#pragma unroll
            for (int w = 0; w < 16; w++) s += wred[w * BT + i];
            y0_sm[t * BT + i] = s;
            int tn = (t + 1 < SEQ) ? (t + 1) : t;
            u_sm[i] = x[(b0 + i) * SEQ + tn];
        }
        __syncthreads();   // sync2: new h/u/y0 visible
    }

    // ---------------- LAYER 2 ----------------
    for (int idx = i; idx < HID * BT; idx += 512) h_sm[idx] = 0.0f;
    __syncthreads();

    for (int t = 0; t < SEQ; t++) {
        float hr[BT];
        step_compute(y0_sm + t * BT, AtC, h_sm, Atg, i, Bv2, hr);
        __syncthreads();
        *reinterpret_cast<float4*>(h_sm + i * BT)     = make_float4(hr[0], hr[1], hr[2], hr[3]);
        *reinterpret_cast<float4*>(h_sm + i * BT + 4) = make_float4(hr[4], hr[5], hr[6], hr[7]);
        __syncthreads();
    }

    // ---------------- logits = h_last @ M2 + b ----------------
    if (i < BT * OUT) {
        int b = i / OUT, o = i % OUT;
        float acc = bias[o];
        for (int k = 0; k < HID; k++) acc += h_sm[k * BT + b] * g_M2[k * OUT + o];
        out[(b0 + b) * OUT + o] = acc;
    }
}

// ---------------- launch -----------------------------------------------------
extern "C" void kernel_launch(void* const* d_in, const int* in_sizes, int n_in,
                              void* d_out, int out_size)
{
    (void)in_sizes; (void)n_in; (void)out_size;
    const float* x  = (const float*)d_in[0];
    const float* C0 = (const float*)d_in[1];
    const float* C1 = (const float*)d_in[2];
    const float* W  = (const float*)d_in[3];
    const float* b  = (const float*)d_in[4];
    float* out = (float*)d_out;

    cudaFuncSetAttribute(ssm_main, cudaFuncAttributeMaxDynamicSharedMemorySize, SMEM_BYTES);

    prep_BL<<<1, HID>>>();
    prep_Ad<<<HID, HID>>>();
    prep_M2<<<HID, 256>>>(C1, W);
    ssm_main<<<NCTA, 512, SMEM_BYTES>>>(x, C0, b, out);
}

// round 11
// speedup vs baseline: 1.0009x; 1.0009x over previous
#include <cuda_runtime.h>
#include <cuda_bf16.h>
#include <math.h>

#define HID 512
#define SEQ 784
#define BATCH 1024
#define OUT 10
#define BT 8          // batch rows per CTA
#define NCTA (BATCH/BT)
#define JC 90         // At rows cached in SMEM

// ---------------- device-global scratch (static: allocation-free) ----------
__device__ double g_BL[HID * HID];      // (I - s/2 A)^-1, fp64
__device__ float  g_At[HID * HID];      // Ad transposed: At[j][i] = Ad[i][j]
__device__ float  g_Bd[HID];
__device__ float  g_M2[HID * OUT];      // C1^T @ W

// ---------------- f32x2 helpers (packed double-rate fp32) ------------------
__device__ __forceinline__ unsigned long long pk2(float a) {
    unsigned long long r;
    asm("mov.b64 %0,{%1,%1};" : "=l"(r) : "f"(a));
    return r;
}
__device__ __forceinline__ unsigned long long mul2(unsigned long long a, unsigned long long b) {
    unsigned long long r;
    asm("mul.rn.f32x2 %0,%1,%2;" : "=l"(r) : "l"(a), "l"(b));
    return r;
}
__device__ __forceinline__ void fma2(unsigned long long& d, unsigned long long a, unsigned long long b) {
    asm("fma.rn.f32x2 %0,%1,%2,%0;" : "+l"(d) : "l"(a), "l"(b));
}
__device__ __forceinline__ float2 up2(unsigned long long v) {
    float2 f;
    asm("mov.b64 {%0,%1},%2;" : "=f"(f.x), "=f"(f.y) : "l"(v));
    return f;
}

// ---------------- prep 1: BL = (I - s/2 A)^-1 via O(N) column recurrence ---
// A is lower-triangular: A[i][j] = -P_i P_j (i>j), A[i][i] = -(i+1), P_i = sqrt(1+2i).
// M[i][j] = (s/2) P_i P_j (i>j), diag d_i = 1 + (s/2)(i+1).
// Column c: x_c = 1/d_c; S = P_c x_c; for i>c: x_i = -(s/2) P_i S / d_i; S += P_i x_i.
__global__ void prep_BL() {
    __shared__ double P[HID], dinv[HID];
    const int t = threadIdx.x;
    const double s2 = 0.5 / (double)SEQ;
    P[t]    = sqrt(1.0 + 2.0 * (double)t);
    dinv[t] = 1.0 / (1.0 + s2 * (double)(t + 1));
    __syncthreads();
    const int c = t;
    double xv = dinv[c];
    g_BL[c * HID + c] = xv;
    double S = P[c] * xv;
    for (int i = c + 1; i < HID; i++) {
        double xi = -(s2 * P[i] * S) * dinv[i];
        g_BL[i * HID + c] = xi;
        S += P[i] * xi;
    }
}

// ---------------- prep 2: Ad = BL @ (I + s/2 A) via per-row prefix scan ----
// Ad[i][j] = BL[i][j]*(1 - s2*(j+1)) - s2*P_j * (pre[i] - pre[j]),
// pre[j] = sum_{k<=j} BL[i][k] P_k;  Bd[i] = (1/SEQ) * pre[i].
__global__ void prep_Ad() {
    const int i = blockIdx.x;
    const int t = threadIdx.x;
    __shared__ double pre[HID];
    const double s2 = 0.5 / (double)SEQ;
    const double Pt = sqrt(1.0 + 2.0 * (double)t);
    const double bl = (t <= i) ? g_BL[i * HID + t] : 0.0;
    pre[t] = bl * Pt;
    __syncthreads();
    for (int off = 1; off < HID; off <<= 1) {
        double add = (t >= off) ? pre[t - off] : 0.0;
        __syncthreads();
        pre[t] += add;
        __syncthreads();
    }
    const double prei = pre[i];
    float at;
    if (t <= i) {
        double dplus = 1.0 - s2 * (double)(t + 1);
        at = (float)(bl * dplus - s2 * Pt * (prei - pre[t]));
    } else {
        at = 0.0f;
    }
    g_At[t * HID + i] = at;   // transposed store
    if (t == i) g_Bd[i] = (float)(prei / (double)SEQ);
}

// ---------------- prep 3: M2 = C1^T @ W  (512 x 10) ------------------------
__global__ void prep_M2(const float* __restrict__ C1, const float* __restrict__ W) {
    const int i = blockIdx.x;      // hidden index
    const int t = threadIdx.x;     // 256 threads
    float acc[OUT];
#pragma unroll
    for (int o = 0; o < OUT; o++) acc[o] = 0.0f;
    for (int k = t; k < HID; k += 256) {
        float c = C1[k * HID + i];
#pragma unroll
        for (int o = 0; o < OUT; o++) acc[o] += c * W[k * OUT + o];
    }
    __shared__ float red[8][OUT];
    const int w = t >> 5, l = t & 31;
#pragma unroll
    for (int o = 0; o < OUT; o++) {
        float v = acc[o];
        for (int s = 16; s; s >>= 1) v += __shfl_xor_sync(0xffffffffu, v, s);
        if (l == 0) red[w][o] = v;
    }
    __syncthreads();
    if (t < OUT) {
        float s = 0.0f;
        for (int w2 = 0; w2 < 8; w2++) s += red[w2][t];
        g_M2[i * OUT + t] = s;
    }
}

// ---------------- main persistent kernel: both SSM layers per batch tile ---
// smem: h[512][8] | y0[784][8] | u[8] | wred[16*8] | AtC[JC][512]
#define SMEM_FLOATS (HID*BT + SEQ*BT + 8 + 128 + JC*HID)
#define SMEM_BYTES (SMEM_FLOATS * 4)

__device__ __forceinline__ void step_compute(
    const float* usrc, const float* AtC, const float* h_sm,
    const float* __restrict__ Atg, int i, unsigned long long Bv2, float hr[BT])
{
    ulonglong2 uA = *reinterpret_cast<const ulonglong2*>(usrc);
    ulonglong2 uB = *reinterpret_cast<const ulonglong2*>(usrc + 4);
    unsigned long long a0 = mul2(Bv2, uA.x);
    unsigned long long a1 = mul2(Bv2, uA.y);
    unsigned long long a2 = mul2(Bv2, uB.x);
    unsigned long long a3 = mul2(Bv2, uB.y);
#pragma unroll 5
    for (int j = 0; j < JC; j++) {
        float a = AtC[j * HID + i];
        unsigned long long ad = pk2(a);
        ulonglong2 hA = *reinterpret_cast<const ulonglong2*>(h_sm + j * BT);
        ulonglong2 hB = *reinterpret_cast<const ulonglong2*>(h_sm + j * BT + 4);
        fma2(a0, ad, hA.x); fma2(a1, ad, hA.y);
        fma2(a2, ad, hB.x); fma2(a3, ad, hB.y);
    }
    const float* ag = Atg;   // = g_At + JC*HID + i
#pragma unroll 4
    for (int j = JC; j < HID; j++) {
        float a = __ldg(ag); ag += HID;
        unsigned long long ad = pk2(a);
        ulonglong2 hA = *reinterpret_cast<const ulonglong2*>(h_sm + j * BT);
        ulonglong2 hB = *reinterpret_cast<const ulonglong2*>(h_sm + j * BT + 4);
        fma2(a0, ad, hA.x); fma2(a1, ad, hA.y);
        fma2(a2, ad, hB.x); fma2(a3, ad, hB.y);
    }
    float2 f;
    f = up2(a0); hr[0] = tanhf(f.x); hr[1] = tanhf(f.y);
    f = up2(a1); hr[2] = tanhf(f.x); hr[3] = tanhf(f.y);
    f = up2(a2); hr[4] = tanhf(f.x); hr[5] = tanhf(f.y);
    f = up2(a3); hr[6] = tanhf(f.x); hr[7] = tanhf(f.y);
}

__global__ void __launch_bounds__(512, 1) ssm_main(
    const float* __restrict__ x, const float* __restrict__ C0,
    const float* __restrict__ bias, float* __restrict__ out)
{
    extern __shared__ float sm[];
    float* h_sm  = sm;                       // HID*BT
    float* y0_sm = sm + HID * BT;            // SEQ*BT
    float* u_sm  = y0_sm + SEQ * BT;         // 8
    float* wred  = u_sm + 8;                 // 16*8
    float* AtC   = wred + 128;               // JC*HID

    const int i  = threadIdx.x;
    const int b0 = blockIdx.x * BT;
    const int warp = i >> 5, lane = i & 31;

    for (int idx = i; idx < JC * HID; idx += 512) AtC[idx] = g_At[idx];
    for (int idx = i; idx < HID * BT; idx += 512) h_sm[idx] = 0.0f;

    const float Bv = g_Bd[i];
    const float c0 = C0[i];
    const unsigned long long Bv2 = pk2(Bv);
    const float* Atg = g_At + (size_t)JC * HID + i;

    if (i < BT) u_sm[i] = x[(b0 + i) * SEQ + 0];
    __syncthreads();

    // ---------------- LAYER 1 ----------------
    for (int t = 0; t < SEQ; t++) {
        float hr[BT];
        step_compute(u_sm, AtC, h_sm, Atg, i, Bv2, hr);

        // y0 partials: y0[b] = sum_i C0[i]*h[b][i]
        float p[BT];
#pragma unroll
        for (int b = 0; b < BT; b++) {
            float v = c0 * hr[b];
            for (int s = 16; s; s >>= 1) v += __shfl_xor_sync(0xffffffffu, v, s);
            p[b] = v;
        }
        if (lane == 0) {
#pragma unroll
            for (int b = 0; b < BT; b++) wred[warp * BT + b] = p[b];
        }
        __syncthreads();   // sync1: all reads of old h/u done; wred written

        *reinterpret_cast<float4*>(h_sm + i * BT)     = make_float4(hr[0], hr[1], hr[2], hr[3]);
        *reinterpret_cast<float4*>(h_sm + i * BT + 4) = make_float4(hr[4], hr[5], hr[6], hr[7]);

        if (i < BT) {
            float s = 0.0f;
#pragma unroll
            for (int w = 0; w < 16; w++) s += wred[w * BT + i];
            y0_sm[t * BT + i] = s;
            int tn = (t + 1 < SEQ) ? (t + 1) : t;
            u_sm[i] = x[(b0 + i) * SEQ + tn];
        }
        __syncthreads();   // sync2: new h/u/y0 visible
    }

    // ---------------- LAYER 2 ----------------
    for (int idx = i; idx < HID * BT; idx += 512) h_sm[idx] = 0.0f;
    __syncthreads();

    for (int t = 0; t < SEQ; t++) {
        float hr[BT];
        step_compute(y0_sm + t * BT, AtC, h_sm, Atg, i, Bv2, hr);
        __syncthreads();
        *reinterpret_cast<float4*>(h_sm + i * BT)     = make_float4(hr[0], hr[1], hr[2], hr[3]);
        *reinterpret_cast<float4*>(h_sm + i * BT + 4) = make_float4(hr[4], hr[5], hr[6], hr[7]);
        __syncthreads();
    }

    // ---------------- logits = h_last @ M2 + b ----------------
    if (i < BT * OUT) {
        int b = i / OUT, o = i % OUT;
        float acc = bias[o];
        for (int k = 0; k < HID; k++) acc += h_sm[k * BT + b] * g_M2[k * OUT + o];
        out[(b0 + b) * OUT + o] = acc;
    }
}

// ---------------- launch -----------------------------------------------------
extern "C" void kernel_launch(void* const* d_in, const int* in_sizes, int n_in,
                              void* d_out, int out_size)
{
    (void)in_sizes; (void)n_in; (void)out_size;
    const float* x  = (const float*)d_in[0];
    const float* C0 = (const float*)d_in[1];
    const float* C1 = (const float*)d_in[2];
    const float* W  = (const float*)d_in[3];
    const float* b  = (const float*)d_in[4];
    float* out = (float*)d_out;

    cudaFuncSetAttribute(ssm_main, cudaFuncAttributeMaxDynamicSharedMemorySize, SMEM_BYTES);

    prep_BL<<<1, HID>>>();
    prep_Ad<<<HID, HID>>>();
    prep_M2<<<HID, 256>>>(C1, W);
    ssm_main<<<NCTA, 512, SMEM_BYTES>>>(x, C0, b, out);
}

// round 12
// speedup vs baseline: 1.0065x; 1.0057x over previous
#include <cuda_runtime.h>
#include <cuda_bf16.h>
#include <math.h>

#define HID 512
#define SEQ 784
#define BATCH 1024
#define OUT 10
#define BT 8          // batch rows per CTA
#define NCTA (BATCH/BT)
#define JC 90         // At rows cached in SMEM

// ---------------- device-global scratch (static: allocation-free) ----------
__device__ double g_BL[HID * HID];      // (I - s/2 A)^-1, fp64
__device__ float  g_At[HID * HID];      // Ad transposed: At[j][i] = Ad[i][j]
__device__ float  g_Bd[HID];
__device__ float  g_M2[HID * OUT];      // C1^T @ W

// ---------------- f32x2 helpers (packed double-rate fp32) ------------------
__device__ __forceinline__ unsigned long long pk2(float a) {
    unsigned long long r;
    asm("mov.b64 %0,{%1,%1};" : "=l"(r) : "f"(a));
    return r;
}
__device__ __forceinline__ unsigned long long mul2(unsigned long long a, unsigned long long b) {
    unsigned long long r;
    asm("mul.rn.f32x2 %0,%1,%2;" : "=l"(r) : "l"(a), "l"(b));
    return r;
}
__device__ __forceinline__ void fma2(unsigned long long& d, unsigned long long a, unsigned long long b) {
    asm("fma.rn.f32x2 %0,%1,%2,%0;" : "+l"(d) : "l"(a), "l"(b));
}
__device__ __forceinline__ float2 up2(unsigned long long v) {
    float2 f;
    asm("mov.b64 {%0,%1},%2;" : "=f"(f.x), "=f"(f.y) : "l"(v));
    return f;
}

// ---------------- prep 1: BL = (I - s/2 A)^-1 via O(N) column recurrence ---
// A is lower-triangular: A[i][j] = -P_i P_j (i>j), A[i][i] = -(i+1), P_i = sqrt(1+2i).
// M[i][j] = (s/2) P_i P_j (i>j), diag d_i = 1 + (s/2)(i+1).
// Column c: x_c = 1/d_c; S = P_c x_c; for i>c: x_i = -(s/2) P_i S / d_i; S += P_i x_i.
__global__ void prep_BL() {
    __shared__ double P[HID], dinv[HID];
    const int t = threadIdx.x;
    const double s2 = 0.5 / (double)SEQ;
    P[t]    = sqrt(1.0 + 2.0 * (double)t);
    dinv[t] = 1.0 / (1.0 + s2 * (double)(t + 1));
    __syncthreads();
    const int c = t;
    double xv = dinv[c];
    g_BL[c * HID + c] = xv;
    double S = P[c] * xv;
    for (int i = c + 1; i < HID; i++) {
        double xi = -(s2 * P[i] * S) * dinv[i];
        g_BL[i * HID + c] = xi;
        S += P[i] * xi;
    }
}

// ---------------- prep 2: Ad = BL @ (I + s/2 A) via per-row prefix scan ----
// Ad[i][j] = BL[i][j]*(1 - s2*(j+1)) - s2*P_j * (pre[i] - pre[j]),
// pre[j] = sum_{k<=j} BL[i][k] P_k;  Bd[i] = (1/SEQ) * pre[i].
__global__ void prep_Ad() {
    const int i = blockIdx.x;
    const int t = threadIdx.x;
    __shared__ double pre[HID];
    const double s2 = 0.5 / (double)SEQ;
    const double Pt = sqrt(1.0 + 2.0 * (double)t);
    const double bl = (t <= i) ? g_BL[i * HID + t] : 0.0;
    pre[t] = bl * Pt;
    __syncthreads();
    for (int off = 1; off < HID; off <<= 1) {
        double add = (t >= off) ? pre[t - off] : 0.0;
        __syncthreads();
        pre[t] += add;
        __syncthreads();
    }
    const double prei = pre[i];
    float at;
    if (t <= i) {
        double dplus = 1.0 - s2 * (double)(t + 1);
        at = (float)(bl * dplus - s2 * Pt * (prei - pre[t]));
    } else {
        at = 0.0f;
    }
    g_At[t * HID + i] = at;   // transposed store
    if (t == i) g_Bd[i] = (float)(prei / (double)SEQ);
}

// ---------------- prep 3: M2 = C1^T @ W  (512 x 10) ------------------------
__global__ void prep_M2(const float* __restrict__ C1, const float* __restrict__ W) {
    const int i = blockIdx.x;      // hidden index
    const int t = threadIdx.x;     // 256 threads
    float acc[OUT];
#pragma unroll
    for (int o = 0; o < OUT; o++) acc[o] = 0.0f;
    for (int k = t; k < HID; k += 256) {
        float c = C1[k * HID + i];
#pragma unroll
        for (int o = 0; o < OUT; o++) acc[o] += c * W[k * OUT + o];
    }
    __shared__ float red[8][OUT];
    const int w = t >> 5, l = t & 31;
#pragma unroll
    for (int o = 0; o < OUT; o++) {
        float v = acc[o];
        for (int s = 16; s; s >>= 1) v += __shfl_xor_sync(0xffffffffu, v, s);
        if (l == 0) red[w][o] = v;
    }
    __syncthreads();
    if (t < OUT) {
        float s = 0.0f;
        for (int w2 = 0; w2 < 8; w2++) s += red[w2][t];
        g_M2[i * OUT + t] = s;
    }
}

// ---------------- main persistent kernel: both SSM layers per batch tile ---
// smem: h[512][8] | y0[784][8] | u[8] | wred[16*8] | AtC[JC][512]
#define SMEM_FLOATS (HID*BT + SEQ*BT + 8 + 128 + JC*HID)
#define SMEM_BYTES (SMEM_FLOATS * 4)

__device__ __forceinline__ void step_compute(
    const float* usrc, const float* AtC, const float* h_sm,
    const float* __restrict__ Atg, int i, unsigned long long Bv2, float hr[BT])
{
    ulonglong2 uA = *reinterpret_cast<const ulonglong2*>(usrc);
    ulonglong2 uB = *reinterpret_cast<const ulonglong2*>(usrc + 4);
    unsigned long long a0 = mul2(Bv2, uA.x);
    unsigned long long a1 = mul2(Bv2, uA.y);
    unsigned long long a2 = mul2(Bv2, uB.x);
    unsigned long long a3 = mul2(Bv2, uB.y);
#pragma unroll 5
    for (int j = 0; j < JC; j++) {
        float a = AtC[j * HID + i];
        unsigned long long ad = pk2(a);
        ulonglong2 hA = *reinterpret_cast<const ulonglong2*>(h_sm + j * BT);
        ulonglong2 hB = *reinterpret_cast<const ulonglong2*>(h_sm + j * BT + 4);
        fma2(a0, ad, hA.x); fma2(a1, ad, hA.y);
        fma2(a2, ad, hB.x); fma2(a3, ad, hB.y);
    }
    const float* ag = Atg;   // = g_At + JC*HID + i
#pragma unroll 4
    for (int j = JC; j < HID; j++) {
        float a = __ldg(ag); ag += HID;
        unsigned long long ad = pk2(a);
        ulonglong2 hA = *reinterpret_cast<const ulonglong2*>(h_sm + j * BT);
        ulonglong2 hB = *reinterpret_cast<const ulonglong2*>(h_sm + j * BT + 4);
        fma2(a0, ad, hA.x); fma2(a1, ad, hA.y);
        fma2(a2, ad, hB.x); fma2(a3, ad, hB.y);
    }
    float2 f;
    f = up2(a0); hr[0] = tanhf(f.x); hr[1] = tanhf(f.y);
    f = up2(a1); hr[2] = tanhf(f.x); hr[3] = tanhf(f.y);
    f = up2(a2); hr[4] = tanhf(f.x); hr[5] = tanhf(f.y);
    f = up2(a3); hr[6] = tanhf(f.x); hr[7] = tanhf(f.y);
}

__global__ void __launch_bounds__(512, 1) ssm_main(
    const float* __restrict__ x, const float* __restrict__ C0,
    const float* __restrict__ bias, float* __restrict__ out)
{
    extern __shared__ float sm[];
    float* h_sm  = sm;                       // HID*BT
    float* y0_sm = sm + HID * BT;            // SEQ*BT
    float* u_sm  = y0_sm + SEQ * BT;         // 8
    float* wred  = u_sm + 8;                 // 16*8
    float* AtC   = wred + 128;               // JC*HID

    const int i  = threadIdx.x;
    const int b0 = blockIdx.x * BT;
    const int warp = i >> 5, lane = i & 31;

    for (int idx = i; idx < JC * HID; idx += 512) AtC[idx] = g_At[idx];
    for (int idx = i; idx < HID * BT; idx += 512) h_sm[idx] = 0.0f;

    const float Bv = g_Bd[i];
    const float c0 = C0[i];
    const unsigned long long Bv2 = pk2(Bv);
    const float* Atg = g_At + (size_t)JC * HID + i;

    if (i < BT) u_sm[i] = x[(b0 + i) * SEQ + 0];
    __syncthreads();

    // ---------------- LAYER 1 ----------------
    for (int t = 0; t < SEQ; t++) {
        float hr[BT];
        step_compute(u_sm, AtC, h_sm, Atg, i, Bv2, hr);

        // y0 partials: y0[b] = sum_i C0[i]*h[b][i]
        float p[BT];
#pragma unroll
        for (int b = 0; b < BT; b++) {
            float v = c0 * hr[b];
            for (int s = 16; s; s >>= 1) v += __shfl_xor_sync(0xffffffffu, v, s);
            p[b] = v;
        }
        if (lane == 0) {
#pragma unroll
            for (int b = 0; b < BT; b++) wred[warp * BT + b] = p[b];
        }
        __syncthreads();   // sync1: all reads of old h/u done; wred written

        *reinterpret_cast<float4*>(h_sm + i * BT)     = make_float4(hr[0], hr[1], hr[2], hr[3]);
        *reinterpret_cast<float4*>(h_sm + i * BT + 4) = make_float4(hr[4], hr[5], hr[6], hr[7]);

        if (i < BT) {
            float s = 0.0f;
#pragma unroll
            for (int w = 0; w < 16; w++) s += wred[w * BT + i];
            y0_sm[t * BT + i] = s;
            int tn = (t + 1 < SEQ) ? (t + 1) : t;
            u_sm[i] = x[(b0 + i) * SEQ + tn];
        }
        __syncthreads();   // sync2: new h/u/y0 visible
    }

    // ---------------- LAYER 2 ----------------
    for (int idx = i; idx < HID * BT; idx += 512) h_sm[idx] = 0.0f;
    __syncthreads();

    for (int t = 0; t < SEQ; t++) {
        float hr[BT];
        step_compute(y0_sm + t * BT, AtC, h_sm, Atg, i, Bv2, hr);
        __syncthreads();
        *reinterpret_cast<float4*>(h_sm + i * BT)     = make_float4(hr[0], hr[1], hr[2], hr[3]);
        *reinterpret_cast<float4*>(h_sm + i * BT + 4) = make_float4(hr[4], hr[5], hr[6], hr[7]);
        __syncthreads();
    }

    // ---------------- logits = h_last @ M2 + b ----------------
    if (i < BT * OUT) {
        int b = i / OUT, o = i % OUT;
        float acc = bias[o];
        for (int k = 0; k < HID; k++) acc += h_sm[k * BT + b] * g_M2[k * OUT + o];
        out[(b0 + b) * OUT + o] = acc;
    }
}

// ---------------- launch -----------------------------------------------------
extern "C" void kernel_launch(void* const* d_in, const int* in_sizes, int n_in,
                              void* d_out, int out_size)
{
    (void)in_sizes; (void)n_in; (void)out_size;
    const float* x  = (const float*)d_in[0];
    const float* C0 = (const float*)d_in[1];
    const float* C1 = (const float*)d_in[2];
    const float* W  = (const float*)d_in[3];
    const float* b  = (const float*)d_in[4];
    float* out = (float*)d_out;

    cudaFuncSetAttribute(ssm_main, cudaFuncAttributeMaxDynamicSharedMemorySize, SMEM_BYTES);

    prep_BL<<<1, HID>>>();
    prep_Ad<<<HID, HID>>>();
    prep_M2<<<HID, 256>>>(C1, W);
    ssm_main<<<NCTA, 512, SMEM_BYTES>>>(x, C0, b, out);
}